// round 2
// baseline (speedup 1.0000x reference)
#include <cuda_runtime.h>

#define NTOT 22743
#define NB   64
#define NEGF -1e9f

// per-anchor masked scores (score if valid else NEG). ~5.8 MB scratch.
__device__ float g_scores[NB * NTOT];

// anchors in pixels: level*3 + a  (w, h)
__constant__ float c_aw[9] = {116.f, 156.f, 373.f,  30.f, 62.f, 59.f,  10.f, 16.f, 33.f};
__constant__ float c_ah[9] = { 90.f, 198.f, 326.f,  61.f, 45.f, 119.f, 13.f, 30.f, 23.f};

// ---------------------------------------------------------------------------
// Kernel A: gate + score every anchor. Writes masked score to g_scores.
// Gate on raw logits (no transcendentals); softmax only for ~17% that pass.
// ---------------------------------------------------------------------------
__global__ void score_kernel(const float* __restrict__ p0,
                             const float* __restrict__ p1,
                             const float* __restrict__ p2) {
    int t = blockIdx.x * blockDim.x + threadIdx.x;
    if (t >= NB * NTOT) return;
    int b = t / NTOT;
    int n = t - b * NTOT;

    const float* rec;
    if (n < 1083) {
        rec = p0 + ((size_t)b * 1083 + n) * 26;
    } else if (n < 5415) {
        rec = p1 + ((size_t)b * 4332 + (n - 1083)) * 26;
    } else {
        rec = p2 + ((size_t)b * 17328 + (n - 5415)) * 26;
    }

    float tobj = rec[4];
    float tloc = rec[5];
    float out = NEGF;
    // obj >= 0.6  <=>  logit >= ln(1.5);  loc >= 0.5 <=> logit >= 0
    if (tobj >= 0.40546510810816444f && tloc >= 0.0f) {
        float l[20];
#pragma unroll
        for (int c = 0; c < 20; c++) l[c] = rec[6 + c];
        float m = l[0];
#pragma unroll
        for (int c = 1; c < 20; c++) m = fmaxf(m, l[c]);
        float ssum = 0.f;
#pragma unroll
        for (int c = 0; c < 20; c++) ssum += __expf(l[c] - m);
        float obj = __fdividef(1.f, 1.f + __expf(-tobj));
        float conf = __fdividef(obj, ssum);          // obj * max(softmax)
        if (conf >= 0.05f) {
            float loc = __fdividef(1.f, 1.f + __expf(-tloc));
            out = sqrtf(conf) * sqrtf(loc);          // (obj*cc)^.5 * loc^.5
        }
    }
    g_scores[t] = out;
}

// ---------------------------------------------------------------------------
// Kernel B: one block per image. Compact valid -> bitonic top-sort ->
// decode 256 candidates -> per-class parallel soft-NMS (one warp per class)
// -> first-8-kept output.
// ---------------------------------------------------------------------------
__global__ __launch_bounds__(1024) void select_nms_kernel(
    const float* __restrict__ p0, const float* __restrict__ p1,
    const float* __restrict__ p2, float* __restrict__ out) {
    extern __shared__ unsigned long long keys[];   // 8192 entries (64 KB dyn)

    __shared__ float4 cbox[256];
    __shared__ float  cval[256];
    __shared__ float  carea[256];
    __shared__ int    ccls[256];
    __shared__ unsigned char kept[256];
    __shared__ unsigned char clist[20][64];
    __shared__ int s_cnt;

    int tid = threadIdx.x;
    int b = blockIdx.x;
    if (tid == 0) s_cnt = 0;
    if (tid < 256) kept[tid] = 0;
    __syncthreads();

    // ---- compact valid scores into 64-bit keys (score_bits << 32 | ~idx) ----
    const float* sc_base = g_scores + (size_t)b * NTOT;
    for (int i = tid; i < NTOT; i += 1024) {
        float sc = sc_base[i];
        if (sc > 0.f) {
            int p = atomicAdd(&s_cnt, 1);
            if (p < 8192)
                keys[p] = ((unsigned long long)__float_as_uint(sc) << 32) |
                          (unsigned)(~(unsigned)i);
        }
    }
    __syncthreads();
    int cnt = min(s_cnt, 8192);
    int n2 = 256;
    while (n2 < cnt) n2 <<= 1;
    for (int i = cnt + tid; i < n2; i += 1024) keys[i] = 0ULL;
    __syncthreads();

    // ---- bitonic sort, descending ----
    for (int k = 2; k <= n2; k <<= 1) {
        for (int j = k >> 1; j > 0; j >>= 1) {
            for (int i = tid; i < n2; i += 1024) {
                int l = i ^ j;
                if (l > i) {
                    unsigned long long a = keys[i], c2 = keys[l];
                    bool desc = ((i & k) == 0);
                    if ((a < c2) == desc) { keys[i] = c2; keys[l] = a; }
                }
            }
            __syncthreads();
        }
    }

    // ---- decode top-256 candidates ----
    if (tid < 256) {
        unsigned long long kk = keys[tid];
        float4 bx = make_float4(0.f, 0.f, 0.f, 0.f);
        int cls = 255;               // never matches a class warp (0..19)
        float val = NEGF;
        float area = 0.f;
        if (kk != 0ULL) {
            unsigned n = ~(unsigned)(kk & 0xFFFFFFFFull);
            val = __uint_as_float((unsigned)(kk >> 32));
            int lvl, r, GG, G; float strd; const float* base;
            if (n < 1083u) {
                lvl = 0; r = (int)n;        GG = 361;  G = 19; strd = 32.f;
                base = p0 + (size_t)b * 1083 * 26;
            } else if (n < 5415u) {
                lvl = 1; r = (int)n - 1083; GG = 1444; G = 38; strd = 16.f;
                base = p1 + (size_t)b * 4332 * 26;
            } else {
                lvl = 2; r = (int)n - 5415; GG = 5776; G = 76; strd = 8.f;
                base = p2 + (size_t)b * 17328 * 26;
            }
            int a = r / GG; int cell = r - a * GG;
            int gy = cell / G; int gx = cell - gy * G;
            const float* rec = base + (size_t)r * 26;
            float tx = rec[0], ty = rec[1], tw = rec[2], th = rec[3];
            float m = rec[6]; int ci = 0;
#pragma unroll
            for (int c = 1; c < 20; c++) {
                float v = rec[6 + c];
                if (v > m) { m = v; ci = c; }
            }
            float sx = __fdividef(1.f, 1.f + __expf(-tx));
            float sy = __fdividef(1.f, 1.f + __expf(-ty));
            float cx = (sx + (float)gx) * strd;
            float cy = (sy + (float)gy) * strd;
            float w = __expf(tw) * c_aw[lvl * 3 + a];
            float h = __expf(th) * c_ah[lvl * 3 + a];
            float x1 = fminf(fmaxf(cx - 0.5f * w, 0.f), 608.f);
            float y1 = fminf(fmaxf(cy - 0.5f * h, 0.f), 608.f);
            float x2 = fminf(fmaxf(cx + 0.5f * w, 0.f), 608.f);
            float y2 = fminf(fmaxf(cy + 0.5f * h, 0.f), 608.f);
            bx = make_float4(x1, y1, x2, y2);
            area = (x2 - x1 + 1.f) * (y2 - y1 + 1.f);
            cls = ci;
        }
        cbox[tid] = bx;
        cval[tid] = val;
        carea[tid] = area;
        ccls[tid] = cls;
    }
    __syncthreads();

    // ---- per-class soft-NMS: warp w handles class w (classes decouple) ----
    int warp = tid >> 5, lane = tid & 31;
    if (warp < 20) {
        int c = warp;
        // gather this class's candidates in candidate order (stable)
        int cntc = 0;
        for (int g = 0; g < 8; g++) {
            int cand = g * 32 + lane;
            bool take = (ccls[cand] == c);
            unsigned mm = __ballot_sync(0xFFFFFFFFu, take);
            if (take) {
                int pos = cntc + __popc(mm & ((1u << lane) - 1u));
                if (pos < 64) clist[c][pos] = (unsigned char)cand;
            }
            cntc += __popc(mm);
        }
        if (cntc > 64) cntc = 64;
        __syncwarp();

        int cand0 = (lane < cntc) ? (int)clist[c][lane] : -1;
        int cand1 = (lane + 32 < cntc) ? (int)clist[c][lane + 32] : -1;
        float s0f = (cand0 >= 0) ? cval[cand0] : NEGF;
        float s1f = (cand1 >= 0) ? cval[cand1] : NEGF;
        float4 b0 = (cand0 >= 0) ? cbox[cand0] : make_float4(0.f, 0.f, 0.f, 0.f);
        float4 b1 = (cand1 >= 0) ? cbox[cand1] : make_float4(0.f, 0.f, 0.f, 0.f);
        float a0 = (cand0 >= 0) ? carea[cand0] : 0.f;
        float a1 = (cand1 >= 0) ? carea[cand1] : 0.f;

        while (true) {
            float sm; int im;
            if (s1f > s0f) { sm = s1f; im = cand1; }
            else           { sm = s0f; im = cand0; }   // tie -> lower cand idx
            unsigned kb = (sm > 0.f) ? __float_as_uint(sm) : 0u;
            unsigned gmax = __reduce_max_sync(0xFFFFFFFFu, kb);
            if (gmax < 0x3DCCCCCDu) break;             // 0.1f as bits
            int mi = (kb == gmax) ? im : 0x7FFFFFFF;
            int j = __reduce_min_sync(0xFFFFFFFFu, mi);
            if (lane == 0) kept[j] = 1;
            float4 bj = cbox[j];
            float aj = carea[j];
            if (cand0 >= 0) {
                if (cand0 == j) s0f = NEGF;
                else {
                    float ix1 = fmaxf(bj.x, b0.x), iy1 = fmaxf(bj.y, b0.y);
                    float ix2 = fminf(bj.z, b0.z), iy2 = fminf(bj.w, b0.w);
                    float inter = fmaxf(ix2 - ix1 + 1.f, 0.f) *
                                  fmaxf(iy2 - iy1 + 1.f, 0.f);
                    float iou = __fdividef(inter, aj + a0 - inter + 1e-16f);
                    s0f *= __expf(-2.f * iou * iou);
                }
            }
            if (cand1 >= 0) {
                if (cand1 == j) s1f = NEGF;
                else {
                    float ix1 = fmaxf(bj.x, b1.x), iy1 = fmaxf(bj.y, b1.y);
                    float ix2 = fminf(bj.z, b1.z), iy2 = fminf(bj.w, b1.w);
                    float inter = fmaxf(ix2 - ix1 + 1.f, 0.f) *
                                  fmaxf(iy2 - iy1 + 1.f, 0.f);
                    float iou = __fdividef(inter, aj + a1 - inter + 1e-16f);
                    s1f *= __expf(-2.f * iou * iou);
                }
            }
        }
    }
    __syncthreads();

    // ---- output: first 8 kept in candidate order (== top-8 by orig score) ----
    if (tid == 0) {
        float* o = out + (size_t)b * 48;
        int outn = 0;
        for (int cnd = 0; cnd < 256 && outn < 8; cnd++) {
            if (kept[cnd]) {
                float4 bb = cbox[cnd];
                o[outn * 6 + 0] = bb.x;
                o[outn * 6 + 1] = bb.y;
                o[outn * 6 + 2] = bb.z;
                o[outn * 6 + 3] = bb.w;
                o[outn * 6 + 4] = cval[cnd];
                o[outn * 6 + 5] = (float)ccls[cnd];
                outn++;
            }
        }
        for (; outn < 8; outn++) {
#pragma unroll
            for (int q = 0; q < 6; q++) o[outn * 6 + q] = 0.f;
        }
    }
}

extern "C" void kernel_launch(void* const* d_in, const int* in_sizes, int n_in,
                              void* d_out, int out_size) {
    const float* p0 = (const float*)d_in[0];
    const float* p1 = (const float*)d_in[1];
    const float* p2 = (const float*)d_in[2];
    float* out = (float*)d_out;

    cudaFuncSetAttribute(select_nms_kernel,
                         cudaFuncAttributeMaxDynamicSharedMemorySize, 65536);

    int total = NB * NTOT;
    score_kernel<<<(total + 255) / 256, 256>>>(p0, p1, p2);
    select_nms_kernel<<<NB, 1024, 65536>>>(p0, p1, p2, out);
}

// round 3
// speedup vs baseline: 1.2986x; 1.2986x over previous
#include <cuda_runtime.h>

#define NTOT 22743
#define NB   64
#define CAP  8192
#define NEGF -1e9f

typedef unsigned long long ull;

// per-image compacted candidate keys: (score_bits << 32) | ~anchor_idx
__device__ ull g_cand[(size_t)NB * CAP];
__device__ int g_cnt[NB];          // zero-initialized; kernel B resets after use

// anchors in pixels: level*3 + a  (w, h)
__constant__ float c_aw[9] = {116.f, 156.f, 373.f,  30.f, 62.f, 59.f,  10.f, 16.f, 33.f};
__constant__ float c_ah[9] = { 90.f, 198.f, 326.f,  61.f, 45.f, 119.f, 13.f, 30.f, 23.f};

// ---------------------------------------------------------------------------
// Kernel A: gate + score every anchor; compact valid keys into g_cand[b].
// Gate on raw logits (no transcendentals); softmax only for ~17% that pass.
// ---------------------------------------------------------------------------
__global__ void score_kernel(const float* __restrict__ p0,
                             const float* __restrict__ p1,
                             const float* __restrict__ p2) {
    int t = blockIdx.x * blockDim.x + threadIdx.x;
    bool active = t < NB * NTOT;
    int b = 0, n = 0;
    float sc = NEGF;

    if (active) {
        b = t / NTOT;
        n = t - b * NTOT;
        const float2* rec2;
        if (n < 1083) {
            rec2 = (const float2*)(p0 + ((size_t)b * 1083 + n) * 26);
        } else if (n < 5415) {
            rec2 = (const float2*)(p1 + ((size_t)b * 4332 + (n - 1083)) * 26);
        } else {
            rec2 = (const float2*)(p2 + ((size_t)b * 17328 + (n - 5415)) * 26);
        }
        float2 gate = __ldg(rec2 + 2);           // floats 4,5 (obj, loc logits)
        // obj >= 0.6 <=> logit >= ln(1.5); loc >= 0.5 <=> logit >= 0
        if (gate.x >= 0.40546510810816444f && gate.y >= 0.0f) {
            float2 l[10];
#pragma unroll
            for (int i = 0; i < 10; i++) l[i] = __ldg(rec2 + 3 + i);   // floats 6..25
            float m = fmaxf(l[0].x, l[0].y);
#pragma unroll
            for (int i = 1; i < 10; i++) m = fmaxf(m, fmaxf(l[i].x, l[i].y));
            float ssum = 0.f;
#pragma unroll
            for (int i = 0; i < 10; i++)
                ssum += __expf(l[i].x - m) + __expf(l[i].y - m);
            float obj = __fdividef(1.f, 1.f + __expf(-gate.x));
            float conf = __fdividef(obj, ssum);                 // obj * max(softmax)
            if (conf >= 0.05f) {
                float loc = __fdividef(1.f, 1.f + __expf(-gate.y));
                sc = sqrtf(conf) * sqrtf(loc);
            }
        }
    }

    bool pass = active && (sc > 0.f);
    unsigned mb = __match_any_sync(0xFFFFFFFFu, b);
    unsigned pm = __ballot_sync(0xFFFFFFFFu, pass);
    if (pass) {
        unsigned grp = mb & pm;
        int lane = threadIdx.x & 31;
        int leader = __ffs(grp) - 1;
        int rank = __popc(grp & ((1u << lane) - 1u));
        int base = 0;
        if (lane == leader) base = atomicAdd(&g_cnt[b], __popc(grp));
        base = __shfl_sync(grp, base, leader);
        int p = base + rank;
        if (p < CAP)
            g_cand[(size_t)b * CAP + p] =
                ((ull)__float_as_uint(sc) << 32) | (unsigned)(~(unsigned)n);
    }
}

// ---------------------------------------------------------------------------
// Kernel B: one block per image. Radix-select top-~256 via score-bit
// histogram -> small bitonic sort -> decode -> per-class parallel soft-NMS
// (one warp per class) -> first-8-kept output.
// ---------------------------------------------------------------------------
__global__ __launch_bounds__(1024) void select_nms_kernel(
    const float* __restrict__ p0, const float* __restrict__ p1,
    const float* __restrict__ p2, float* __restrict__ out) {

    __shared__ ull    keys2[2048];
    __shared__ int    hist[1024];
    __shared__ int    suf[1024];
    __shared__ float4 cbox[256];
    __shared__ float  cval[256];
    __shared__ float  carea[256];
    __shared__ int    ccls[256];
    __shared__ unsigned char kept[256];
    __shared__ unsigned char clist[20][64];
    __shared__ int s_T, s_col, s_cnt;

    int tid = threadIdx.x;
    int b = blockIdx.x;

    if (tid == 0) {
        s_cnt = min(g_cnt[b], CAP);
        g_cnt[b] = 0;                       // reset for next call (graph-safe)
        s_col = 0;
        s_T = 0;
    }
    hist[tid] = 0;
    if (tid < 256) kept[tid] = 0;
    __syncthreads();

    int cnt = s_cnt;
    const ull* cand = g_cand + (size_t)b * CAP;

    // ---- histogram of score bits (bucket = (bits>>15) - 0x7C00) ----
    for (int i = tid; i < cnt; i += 1024) {
        unsigned sb = (unsigned)(__ldg(cand + i) >> 32);
        int bk = min(max((int)(sb >> 15) - 0x7C00, 0), 1023);
        atomicAdd(&hist[bk], 1);
    }
    __syncthreads();

    // ---- inclusive suffix scan (Hillis-Steele) ----
    suf[tid] = hist[tid];
    __syncthreads();
    for (int s = 1; s < 1024; s <<= 1) {
        int v = suf[tid];
        if (tid + s < 1024) v += suf[tid + s];
        __syncthreads();
        suf[tid] = v;
        __syncthreads();
    }
    // threshold bucket T: largest i with suffix[i] >= 256 (0 if total < 256)
    if (suf[tid] >= 256 && (tid == 1023 || suf[tid + 1] < 256)) s_T = tid;
    __syncthreads();
    int T = s_T;

    // ---- compact entries in buckets >= T ----
    for (int i = tid; i < cnt; i += 1024) {
        ull k = __ldg(cand + i);
        unsigned sb = (unsigned)(k >> 32);
        int bk = min(max((int)(sb >> 15) - 0x7C00, 0), 1023);
        if (bk >= T) {
            int p = atomicAdd(&s_col, 1);
            if (p < 2048) keys2[p] = k;
        }
    }
    __syncthreads();
    int col = min(s_col, 2048);
    int n2 = 256;
    while (n2 < col) n2 <<= 1;
    for (int i = col + tid; i < n2; i += 1024) keys2[i] = 0ULL;
    __syncthreads();

    // ---- bitonic sort (descending) over n2 <= 2048 ----
    for (int k = 2; k <= n2; k <<= 1) {
        for (int j = k >> 1; j > 0; j >>= 1) {
            for (int i = tid; i < n2; i += 1024) {
                int l = i ^ j;
                if (l > i) {
                    ull a = keys2[i], c2 = keys2[l];
                    bool desc = ((i & k) == 0);
                    if ((a < c2) == desc) { keys2[i] = c2; keys2[l] = a; }
                }
            }
            __syncthreads();
        }
    }

    // ---- decode top-256 candidates ----
    if (tid < 256) {
        ull kk = keys2[tid];
        float4 bx = make_float4(0.f, 0.f, 0.f, 0.f);
        int cls = 255;              // never matches a class warp (0..19)
        float val = NEGF;
        float area = 0.f;
        if (kk != 0ULL) {
            unsigned n = ~(unsigned)(kk & 0xFFFFFFFFull);
            val = __uint_as_float((unsigned)(kk >> 32));
            int lvl, r, GG, G; float strd; const float* base;
            if (n < 1083u) {
                lvl = 0; r = (int)n;        GG = 361;  G = 19; strd = 32.f;
                base = p0 + (size_t)b * 1083 * 26;
            } else if (n < 5415u) {
                lvl = 1; r = (int)n - 1083; GG = 1444; G = 38; strd = 16.f;
                base = p1 + (size_t)b * 4332 * 26;
            } else {
                lvl = 2; r = (int)n - 5415; GG = 5776; G = 76; strd = 8.f;
                base = p2 + (size_t)b * 17328 * 26;
            }
            int a = r / GG; int cell = r - a * GG;
            int gy = cell / G; int gx = cell - gy * G;
            const float* rec = base + (size_t)r * 26;
            float tx = rec[0], ty = rec[1], tw = rec[2], th = rec[3];
            float m = rec[6]; int ci = 0;
#pragma unroll
            for (int c = 1; c < 20; c++) {
                float v = rec[6 + c];
                if (v > m) { m = v; ci = c; }
            }
            float sx = __fdividef(1.f, 1.f + __expf(-tx));
            float sy = __fdividef(1.f, 1.f + __expf(-ty));
            float cx = (sx + (float)gx) * strd;
            float cy = (sy + (float)gy) * strd;
            float w = __expf(tw) * c_aw[lvl * 3 + a];
            float h = __expf(th) * c_ah[lvl * 3 + a];
            float x1 = fminf(fmaxf(cx - 0.5f * w, 0.f), 608.f);
            float y1 = fminf(fmaxf(cy - 0.5f * h, 0.f), 608.f);
            float x2 = fminf(fmaxf(cx + 0.5f * w, 0.f), 608.f);
            float y2 = fminf(fmaxf(cy + 0.5f * h, 0.f), 608.f);
            bx = make_float4(x1, y1, x2, y2);
            area = (x2 - x1 + 1.f) * (y2 - y1 + 1.f);
            cls = ci;
        }
        cbox[tid] = bx;
        cval[tid] = val;
        carea[tid] = area;
        ccls[tid] = cls;
    }
    __syncthreads();

    // ---- per-class soft-NMS: warp w handles class w (classes decouple) ----
    int warp = tid >> 5, lane = tid & 31;
    if (warp < 20) {
        int c = warp;
        int cntc = 0;
        for (int g = 0; g < 8; g++) {
            int cand_i = g * 32 + lane;
            bool take = (ccls[cand_i] == c);
            unsigned mm = __ballot_sync(0xFFFFFFFFu, take);
            if (take) {
                int pos = cntc + __popc(mm & ((1u << lane) - 1u));
                if (pos < 64) clist[c][pos] = (unsigned char)cand_i;
            }
            cntc += __popc(mm);
        }
        if (cntc > 64) cntc = 64;
        __syncwarp();

        int cand0 = (lane < cntc) ? (int)clist[c][lane] : -1;
        int cand1 = (lane + 32 < cntc) ? (int)clist[c][lane + 32] : -1;
        float s0f = (cand0 >= 0) ? cval[cand0] : NEGF;
        float s1f = (cand1 >= 0) ? cval[cand1] : NEGF;
        float4 b0 = (cand0 >= 0) ? cbox[cand0] : make_float4(0.f, 0.f, 0.f, 0.f);
        float4 b1 = (cand1 >= 0) ? cbox[cand1] : make_float4(0.f, 0.f, 0.f, 0.f);
        float a0 = (cand0 >= 0) ? carea[cand0] : 0.f;
        float a1 = (cand1 >= 0) ? carea[cand1] : 0.f;

        while (true) {
            float sm; int im;
            if (s1f > s0f) { sm = s1f; im = cand1; }
            else           { sm = s0f; im = cand0; }   // tie -> lower cand idx
            unsigned kb = (sm > 0.f) ? __float_as_uint(sm) : 0u;
            unsigned gmax = __reduce_max_sync(0xFFFFFFFFu, kb);
            if (gmax < 0x3DCCCCCDu) break;             // 0.1f as bits
            int mi = (kb == gmax) ? im : 0x7FFFFFFF;
            int j = __reduce_min_sync(0xFFFFFFFFu, mi);
            if (lane == 0) kept[j] = 1;
            float4 bj = cbox[j];
            float aj = carea[j];
            if (cand0 >= 0) {
                if (cand0 == j) s0f = NEGF;
                else {
                    float ix1 = fmaxf(bj.x, b0.x), iy1 = fmaxf(bj.y, b0.y);
                    float ix2 = fminf(bj.z, b0.z), iy2 = fminf(bj.w, b0.w);
                    float inter = fmaxf(ix2 - ix1 + 1.f, 0.f) *
                                  fmaxf(iy2 - iy1 + 1.f, 0.f);
                    float iou = __fdividef(inter, aj + a0 - inter + 1e-16f);
                    s0f *= __expf(-2.f * iou * iou);
                }
            }
            if (cand1 >= 0) {
                if (cand1 == j) s1f = NEGF;
                else {
                    float ix1 = fmaxf(bj.x, b1.x), iy1 = fmaxf(bj.y, b1.y);
                    float ix2 = fminf(bj.z, b1.z), iy2 = fminf(bj.w, b1.w);
                    float inter = fmaxf(ix2 - ix1 + 1.f, 0.f) *
                                  fmaxf(iy2 - iy1 + 1.f, 0.f);
                    float iou = __fdividef(inter, aj + a1 - inter + 1e-16f);
                    s1f *= __expf(-2.f * iou * iou);
                }
            }
        }
    }
    __syncthreads();

    // ---- output: first 8 kept in candidate order (== top-8 by orig score) ----
    if (tid == 0) {
        float* o = out + (size_t)b * 48;
        int outn = 0;
        for (int cnd = 0; cnd < 256 && outn < 8; cnd++) {
            if (kept[cnd]) {
                float4 bb = cbox[cnd];
                o[outn * 6 + 0] = bb.x;
                o[outn * 6 + 1] = bb.y;
                o[outn * 6 + 2] = bb.z;
                o[outn * 6 + 3] = bb.w;
                o[outn * 6 + 4] = cval[cnd];
                o[outn * 6 + 5] = (float)ccls[cnd];
                outn++;
            }
        }
        for (; outn < 8; outn++) {
#pragma unroll
            for (int q = 0; q < 6; q++) o[outn * 6 + q] = 0.f;
        }
    }
}

extern "C" void kernel_launch(void* const* d_in, const int* in_sizes, int n_in,
                              void* d_out, int out_size) {
    const float* p0 = (const float*)d_in[0];
    const float* p1 = (const float*)d_in[1];
    const float* p2 = (const float*)d_in[2];
    float* out = (float*)d_out;

    int total = NB * NTOT;
    score_kernel<<<(total + 255) / 256, 256>>>(p0, p1, p2);
    select_nms_kernel<<<NB, 1024>>>(p0, p1, p2, out);
}

// round 4
// speedup vs baseline: 1.6159x; 1.2443x over previous
#include <cuda_runtime.h>

#define NTOT  22743
#define NB    64
#define TOTAL (NB * NTOT)
#define CAP   8192
#define NEGF  -1e9f

#define BLKA  256
#define RPT   8
#define CHUNK (BLKA * RPT)

typedef unsigned long long ull;

// per-image compacted candidate keys: (score_bits << 32) | ~anchor_idx
__device__ ull g_cand[(size_t)NB * CAP];
__device__ int g_cnt[NB];          // zero-initialized; kernel B resets after use

// anchors in pixels: level*3 + a  (w, h)
__constant__ float c_aw[9] = {116.f, 156.f, 373.f,  30.f, 62.f, 59.f,  10.f, 16.f, 33.f};
__constant__ float c_ah[9] = { 90.f, 198.f, 326.f,  61.f, 45.f, 119.f, 13.f, 30.f, 23.f};

__device__ __forceinline__ const float2* rec_ptr(const float* p0, const float* p1,
                                                 const float* p2, int b, int n) {
    if (n < 1083)  return (const float2*)(p0 + ((size_t)b * 1083 + n) * 26);
    if (n < 5415)  return (const float2*)(p1 + ((size_t)b * 4332 + (n - 1083)) * 26);
    return (const float2*)(p2 + ((size_t)b * 17328 + (n - 5415)) * 26);
}

// ---------------------------------------------------------------------------
// Kernel A: batched gate loads (MLP=8) -> smem work queue -> dense softmax.
// Gate on raw logits (no transcendentals). Valid keys pushed to g_cand[b].
// ---------------------------------------------------------------------------
__global__ __launch_bounds__(BLKA) void score_kernel(
    const float* __restrict__ p0, const float* __restrict__ p1,
    const float* __restrict__ p2) {

    __shared__ int q[CHUNK];
    __shared__ int qn;

    int tid = threadIdx.x;
    int lane = tid & 31;
    if (tid == 0) qn = 0;
    __syncthreads();

    int base = blockIdx.x * CHUNK;

    // ---- phase 1: 8 independent gate loads per thread ----
    float2 gate[RPT];
    int idx[RPT];
#pragma unroll
    for (int r = 0; r < RPT; r++) {
        int t = base + r * BLKA + tid;
        idx[r] = t;
        if (t < TOTAL) {
            int b = t / NTOT;
            int n = t - b * NTOT;
            gate[r] = __ldg(rec_ptr(p0, p1, p2, b, n) + 2);   // floats 4,5
        } else {
            gate[r] = make_float2(NEGF, NEGF);
        }
    }

    // obj >= 0.6 <=> logit >= ln(1.5); loc >= 0.5 <=> logit >= 0
#pragma unroll
    for (int r = 0; r < RPT; r++) {
        bool pass = (idx[r] < TOTAL) &&
                    (gate[r].x >= 0.40546510810816444f) && (gate[r].y >= 0.0f);
        unsigned m = __ballot_sync(0xFFFFFFFFu, pass);
        if (pass) {
            int leader = __ffs(m) - 1;
            int rank = __popc(m & ((1u << lane) - 1u));
            int bp = 0;
            if (lane == leader) bp = atomicAdd(&qn, __popc(m));
            bp = __shfl_sync(m, bp, leader);
            q[bp + rank] = idx[r];
        }
    }
    __syncthreads();

    // ---- phase 2: dense softmax over queued records ----
    int tot = qn;
    for (int i = tid; i < tot; i += BLKA) {
        int t = q[i];
        int b = t / NTOT;
        int n = t - b * NTOT;
        const float2* rec2 = rec_ptr(p0, p1, p2, b, n);

        float2 g = __ldg(rec2 + 2);
        float2 l[10];
#pragma unroll
        for (int k = 0; k < 10; k++) l[k] = __ldg(rec2 + 3 + k);  // floats 6..25
        float mx = fmaxf(l[0].x, l[0].y);
#pragma unroll
        for (int k = 1; k < 10; k++) mx = fmaxf(mx, fmaxf(l[k].x, l[k].y));
        float ssum = 0.f;
#pragma unroll
        for (int k = 0; k < 10; k++)
            ssum += __expf(l[k].x - mx) + __expf(l[k].y - mx);
        float obj = __fdividef(1.f, 1.f + __expf(-g.x));
        float conf = __fdividef(obj, ssum);                 // obj * max(softmax)
        float sc = NEGF;
        if (conf >= 0.05f) {
            float loc = __fdividef(1.f, 1.f + __expf(-g.y));
            sc = sqrtf(conf) * sqrtf(loc);
        }

        bool push = sc > 0.f;
        unsigned mb = __match_any_sync(__activemask(), b);
        unsigned pm = __ballot_sync(__activemask(), push);
        if (push) {
            unsigned grp = mb & pm;
            int leader = __ffs(grp) - 1;
            int rank = __popc(grp & ((1u << lane) - 1u));
            int bp = 0;
            if (lane == leader) bp = atomicAdd(&g_cnt[b], __popc(grp));
            bp = __shfl_sync(grp, bp, leader);
            int p = bp + rank;
            if (p < CAP)
                g_cand[(size_t)b * CAP + p] =
                    ((ull)__float_as_uint(sc) << 32) | (unsigned)(~(unsigned)n);
        }
    }
}

// ---------------------------------------------------------------------------
// Kernel B: one block per image. Radix-select (histogram + warp-shuffle
// suffix scan) -> low-barrier bitonic sort -> decode -> per-class parallel
// soft-NMS (one warp per class) -> parallel top-8 output.
// ---------------------------------------------------------------------------
__global__ __launch_bounds__(1024) void select_nms_kernel(
    const float* __restrict__ p0, const float* __restrict__ p1,
    const float* __restrict__ p2, float* __restrict__ out) {

    __shared__ ull    keys2[2048];
    __shared__ int    hist[1024];
    __shared__ int    suf[1024];
    __shared__ int    wsum[32];
    __shared__ int    wsuf[32];
    __shared__ float4 cbox[256];
    __shared__ float  cval[256];
    __shared__ float  carea[256];
    __shared__ int    ccls[256];
    __shared__ unsigned char kept[256];
    __shared__ unsigned char clist[20][64];
    __shared__ unsigned kmask[8];
    __shared__ int s_T, s_col, s_cnt;

    int tid = threadIdx.x;
    int lane = tid & 31;
    int w = tid >> 5;
    int b = blockIdx.x;

    if (tid == 0) {
        s_cnt = min(g_cnt[b], CAP);
        g_cnt[b] = 0;                        // reset for next call (graph-safe)
        s_col = 0;
        s_T = 0;
    }
    hist[tid] = 0;
    if (tid < 256) kept[tid] = 0;
    __syncthreads();

    int cnt = s_cnt;
    const ull* cand = g_cand + (size_t)b * CAP;

    // ---- histogram of score bits (bucket = (bits>>15) - 0x7C00) ----
    for (int i = tid; i < cnt; i += 1024) {
        unsigned sb = (unsigned)(__ldg(cand + i) >> 32);
        int bk = min(max((int)(sb >> 15) - 0x7C00, 0), 1023);
        atomicAdd(&hist[bk], 1);
    }
    __syncthreads();

    // ---- suffix scan via warp shuffles (4 barriers) ----
    int v = hist[tid];
#pragma unroll
    for (int s = 1; s < 32; s <<= 1) {
        int t2 = __shfl_down_sync(0xFFFFFFFFu, v, s);
        if (lane + s < 32) v += t2;
    }
    if (lane == 0) wsum[w] = v;              // chunk total (suffix at lane 0)
    __syncthreads();
    if (w == 0) {
        int x = wsum[lane];
        int tot0 = x;
#pragma unroll
        for (int s = 1; s < 32; s <<= 1) {
            int t2 = __shfl_down_sync(0xFFFFFFFFu, x, s);
            if (lane + s < 32) x += t2;
        }
        wsuf[lane] = x - tot0;               // exclusive suffix of later warps
    }
    __syncthreads();
    int sufv = v + wsuf[w];
    suf[tid] = sufv;
    __syncthreads();
    // threshold bucket T: largest i with suffix[i] >= 256 (0 if total < 256)
    if (sufv >= 256 && (tid == 1023 || suf[tid + 1] < 256)) s_T = tid;
    __syncthreads();
    int T = s_T;

    // ---- compact entries in buckets >= T ----
    for (int i = tid; i < cnt; i += 1024) {
        ull k = __ldg(cand + i);
        unsigned sb = (unsigned)(k >> 32);
        int bk = min(max((int)(sb >> 15) - 0x7C00, 0), 1023);
        if (bk >= T) {
            int p = atomicAdd(&s_col, 1);
            if (p < 2048) keys2[p] = k;
        }
    }
    __syncthreads();
    int col = min(s_col, 2048);
    int n2 = 256;
    while (n2 < col) n2 <<= 1;
    for (int i = col + tid; i < n2; i += 1024) keys2[i] = 0ULL;
    __syncthreads();

    // ---- bitonic sort (descending); j<32 passes are warp-local ----
    for (int k = 2; k <= n2; k <<= 1) {
        for (int j = k >> 1; j > 0; j >>= 1) {
            for (int i = tid; i < n2; i += 1024) {
                int l = i ^ j;
                if (l > i) {
                    ull a = keys2[i], c2 = keys2[l];
                    bool desc = ((i & k) == 0);
                    if ((a < c2) == desc) { keys2[i] = c2; keys2[l] = a; }
                }
            }
            if (j >= 32) __syncthreads(); else __syncwarp();
        }
    }
    __syncthreads();

    // ---- decode top-256 candidates ----
    if (tid < 256) {
        ull kk = keys2[tid];
        float4 bx = make_float4(0.f, 0.f, 0.f, 0.f);
        int cls = 255;               // never matches a class warp (0..19)
        float val = NEGF;
        float area = 0.f;
        if (kk != 0ULL) {
            unsigned n = ~(unsigned)(kk & 0xFFFFFFFFull);
            val = __uint_as_float((unsigned)(kk >> 32));
            int lvl, r, GG, G; float strd; const float* base;
            if (n < 1083u) {
                lvl = 0; r = (int)n;        GG = 361;  G = 19; strd = 32.f;
                base = p0 + (size_t)b * 1083 * 26;
            } else if (n < 5415u) {
                lvl = 1; r = (int)n - 1083; GG = 1444; G = 38; strd = 16.f;
                base = p1 + (size_t)b * 4332 * 26;
            } else {
                lvl = 2; r = (int)n - 5415; GG = 5776; G = 76; strd = 8.f;
                base = p2 + (size_t)b * 17328 * 26;
            }
            int a = r / GG; int cell = r - a * GG;
            int gy = cell / G; int gx = cell - gy * G;
            const float* rec = base + (size_t)r * 26;
            float tx = rec[0], ty = rec[1], tw = rec[2], th = rec[3];
            float m = rec[6]; int ci = 0;
#pragma unroll
            for (int c = 1; c < 20; c++) {
                float vv = rec[6 + c];
                if (vv > m) { m = vv; ci = c; }
            }
            float sx = __fdividef(1.f, 1.f + __expf(-tx));
            float sy = __fdividef(1.f, 1.f + __expf(-ty));
            float cx = (sx + (float)gx) * strd;
            float cy = (sy + (float)gy) * strd;
            float ww2 = __expf(tw) * c_aw[lvl * 3 + a];
            float hh = __expf(th) * c_ah[lvl * 3 + a];
            float x1 = fminf(fmaxf(cx - 0.5f * ww2, 0.f), 608.f);
            float y1 = fminf(fmaxf(cy - 0.5f * hh, 0.f), 608.f);
            float x2 = fminf(fmaxf(cx + 0.5f * ww2, 0.f), 608.f);
            float y2 = fminf(fmaxf(cy + 0.5f * hh, 0.f), 608.f);
            bx = make_float4(x1, y1, x2, y2);
            area = (x2 - x1 + 1.f) * (y2 - y1 + 1.f);
            cls = ci;
        }
        cbox[tid] = bx;
        cval[tid] = val;
        carea[tid] = area;
        ccls[tid] = cls;
    }
    __syncthreads();

    // ---- per-class soft-NMS: warp w handles class w (classes decouple) ----
    if (w < 20) {
        int c = w;
        int cntc = 0;
        for (int g = 0; g < 8; g++) {
            int ci2 = g * 32 + lane;
            bool take = (ccls[ci2] == c);
            unsigned mm = __ballot_sync(0xFFFFFFFFu, take);
            if (take) {
                int pos = cntc + __popc(mm & ((1u << lane) - 1u));
                if (pos < 64) clist[c][pos] = (unsigned char)ci2;
            }
            cntc += __popc(mm);
        }
        if (cntc > 64) cntc = 64;
        __syncwarp();

        int cand0 = (lane < cntc) ? (int)clist[c][lane] : -1;
        int cand1 = (lane + 32 < cntc) ? (int)clist[c][lane + 32] : -1;
        float s0f = (cand0 >= 0) ? cval[cand0] : NEGF;
        float s1f = (cand1 >= 0) ? cval[cand1] : NEGF;
        float4 b0 = (cand0 >= 0) ? cbox[cand0] : make_float4(0.f, 0.f, 0.f, 0.f);
        float4 b1 = (cand1 >= 0) ? cbox[cand1] : make_float4(0.f, 0.f, 0.f, 0.f);
        float a0 = (cand0 >= 0) ? carea[cand0] : 0.f;
        float a1 = (cand1 >= 0) ? carea[cand1] : 0.f;

        while (true) {
            float sm; int im;
            if (s1f > s0f) { sm = s1f; im = cand1; }
            else           { sm = s0f; im = cand0; }   // tie -> lower cand idx
            unsigned kb = (sm > 0.f) ? __float_as_uint(sm) : 0u;
            unsigned gmax = __reduce_max_sync(0xFFFFFFFFu, kb);
            if (gmax < 0x3DCCCCCDu) break;             // 0.1f as bits
            int mi = (kb == gmax) ? im : 0x7FFFFFFF;
            int j = __reduce_min_sync(0xFFFFFFFFu, mi);
            if (lane == 0) kept[j] = 1;
            float4 bj = cbox[j];
            float aj = carea[j];
            if (cand0 >= 0) {
                if (cand0 == j) s0f = NEGF;
                else {
                    float ix1 = fmaxf(bj.x, b0.x), iy1 = fmaxf(bj.y, b0.y);
                    float ix2 = fminf(bj.z, b0.z), iy2 = fminf(bj.w, b0.w);
                    float inter = fmaxf(ix2 - ix1 + 1.f, 0.f) *
                                  fmaxf(iy2 - iy1 + 1.f, 0.f);
                    float iou = __fdividef(inter, aj + a0 - inter + 1e-16f);
                    s0f *= __expf(-2.f * iou * iou);
                }
            }
            if (cand1 >= 0) {
                if (cand1 == j) s1f = NEGF;
                else {
                    float ix1 = fmaxf(bj.x, b1.x), iy1 = fmaxf(bj.y, b1.y);
                    float ix2 = fminf(bj.z, b1.z), iy2 = fminf(bj.w, b1.w);
                    float inter = fmaxf(ix2 - ix1 + 1.f, 0.f) *
                                  fmaxf(iy2 - iy1 + 1.f, 0.f);
                    float iou = __fdividef(inter, aj + a1 - inter + 1e-16f);
                    s1f *= __expf(-2.f * iou * iou);
                }
            }
        }
    }
    __syncthreads();

    // ---- parallel output: rank kept candidates, write first 8 ----
    if (tid < 256) {
        unsigned bal = __ballot_sync(0xFFFFFFFFu, kept[tid] != 0);
        if (lane == 0) kmask[tid >> 5] = bal;
    }
    __syncthreads();
    if (tid < 256 && kept[tid]) {
        int pre = 0;
#pragma unroll
        for (int ww = 0; ww < 8; ww++)
            if (ww < (tid >> 5)) pre += __popc(kmask[ww]);
        pre += __popc(kmask[tid >> 5] & ((1u << lane) - 1u));
        if (pre < 8) {
            float* o = out + (size_t)b * 48 + pre * 6;
            float4 bb = cbox[tid];
            o[0] = bb.x; o[1] = bb.y; o[2] = bb.z; o[3] = bb.w;
            o[4] = cval[tid];
            o[5] = (float)ccls[tid];
        }
    }
    if (tid >= 256 && tid < 264) {
        int K = 0;
#pragma unroll
        for (int ww = 0; ww < 8; ww++) K += __popc(kmask[ww]);
        int slot = tid - 256;
        if (slot >= K) {
            float* o = out + (size_t)b * 48 + slot * 6;
#pragma unroll
            for (int q2 = 0; q2 < 6; q2++) o[q2] = 0.f;
        }
    }
}

extern "C" void kernel_launch(void* const* d_in, const int* in_sizes, int n_in,
                              void* d_out, int out_size) {
    const float* p0 = (const float*)d_in[0];
    const float* p1 = (const float*)d_in[1];
    const float* p2 = (const float*)d_in[2];
    float* out = (float*)d_out;

    int gridA = (TOTAL + CHUNK - 1) / CHUNK;
    score_kernel<<<gridA, BLKA>>>(p0, p1, p2);
    select_nms_kernel<<<NB, 1024>>>(p0, p1, p2, out);
}